// round 5
// baseline (speedup 1.0000x reference)
#include <cuda_runtime.h>
#include <math.h>

#define BATCH 2048
#define T 50
#define D 256
#define NEGC (-100000.0f)
#define INV_SQRT_D 0.0625f

typedef unsigned long long u64;

// ---------------- device scratch ----------------
__device__ float g_Aqk[D * D];
__device__ float g_u[D];
__device__ float g_qrs[D];
__device__ float g_wv[D];
__device__ float g_ksum[D];
__device__ float g_scal[3];
__device__ float g_Y[BATCH * D];
__device__ float g_s1[BATCH];
__device__ float g_s2[BATCH];
__device__ float g_Z[BATCH * D];

// ---------------- f32x2 helpers ----------------
__device__ __forceinline__ void ffma2(u64& d, u64 a, u64 b) {
    asm("fma.rn.f32x2 %0, %1, %2, %0;" : "+l"(d) : "l"(a), "l"(b));
}
__device__ __forceinline__ float2 unpack2(u64 v) {
    float2 r;
    asm("mov.b64 {%0, %1}, %2;" : "=f"(r.x), "=f"(r.y) : "l"(v));
    return r;
}
__device__ __forceinline__ u64 pack_dup(float v) {
    u64 r;
    asm("mov.b64 %0, {%1, %1};" : "=l"(r) : "f"(v));
    return r;
}
__device__ __forceinline__ float dot4(float4 a, float4 b) {
    return a.x * b.x + a.y * b.y + a.z * b.z + a.w * b.w;
}

// ---------------- K1: prep ----------------
__global__ __launch_bounds__(256) void prep_kernel(const float* __restrict__ Wq,
                                                   const float* __restrict__ bq,
                                                   const float* __restrict__ Wk,
                                                   const float* __restrict__ bk) {
    __shared__ float Aw[32][16];
    __shared__ float Bw[32][16];
    __shared__ float s_bq[32], s_bk[32];
    int tid = threadIdx.x;
    int tx = tid & 15, ty = tid >> 4;
    int m0 = blockIdx.y * 16, n0 = blockIdx.x * 16;
    float acc = 0.f;
    float e0v = 0.f, e1v = 0.f;
    bool do_u = (blockIdx.x == 0) && (ty == 0);
    bool do_w = (blockIdx.y == 0) && (ty == 1);

    for (int e0 = 0; e0 < D; e0 += 32) {
        #pragma unroll
        for (int i = 0; i < 2; i++) {
            int idx = tid + i * 256;
            int r = idx >> 4, c = idx & 15;
            Aw[r][c] = Wq[(e0 + r) * D + m0 + c];
            Bw[r][c] = Wk[(e0 + r) * D + n0 + c];
        }
        if (tid < 32) {
            s_bq[tid] = bq[e0 + tid];
            s_bk[tid] = bk[e0 + tid];
        }
        __syncthreads();
        #pragma unroll
        for (int e = 0; e < 32; e++) acc += Aw[e][ty] * Bw[e][tx];
        if (do_u) {
            #pragma unroll
            for (int e = 0; e < 32; e++) {
                float w = Aw[e][tx];
                e0v += s_bk[e] * w;
                e1v += w;
            }
        }
        if (do_w) {
            #pragma unroll
            for (int e = 0; e < 32; e++) {
                float w = Bw[e][tx];
                e0v += s_bq[e] * w;
                e1v += w;
            }
        }
        __syncthreads();
    }
    g_Aqk[(m0 + ty) * D + n0 + tx] = acc;
    if (do_u) { g_u[m0 + tx] = e0v; g_qrs[m0 + tx] = e1v; }
    if (do_w) { g_wv[n0 + tx] = e0v; g_ksum[n0 + tx] = e1v; }
    if (blockIdx.x == 0 && blockIdx.y == 0 && tid < 32) {
        float a0 = 0.f, a1 = 0.f, a2 = 0.f;
        #pragma unroll
        for (int j = 0; j < 8; j++) {
            int e = tid + 32 * j;
            float q = bq[e], k = bk[e];
            a0 += q * k; a1 += q; a2 += k;
        }
        #pragma unroll
        for (int o = 16; o > 0; o >>= 1) {
            a0 += __shfl_xor_sync(0xffffffffu, a0, o);
            a1 += __shfl_xor_sync(0xffffffffu, a1, o);
            a2 += __shfl_xor_sync(0xffffffffu, a2, o);
        }
        if (tid == 0) { g_scal[0] = a0; g_scal[1] = a1; g_scal[2] = a2; }
    }
}

// ---------------- K2: Y = (xq*td) @ Aqk + wv ; s1,s2 ----------------
// 32m x 64n tile, BK=32, 128 threads, thread tile 4m x 4n via f32x2.
// A k-major (natural m-pairs), B duplicated at fill.
__global__ __launch_bounds__(128) void gemm_y(const float* __restrict__ x,
                                              const float* __restrict__ td) {
    __shared__ __align__(16) float As[32 * 32];    // [k][m]
    __shared__ __align__(16) u64 Bs2[32 * 64];     // [k][n] dup pairs
    __shared__ float sdu[128], sdq[128];
    int tid = threadIdx.x;
    int m0 = blockIdx.y * 32, n0 = blockIdx.x * 64;
    int tx = tid & 15, ty = tid >> 4;

    // A fill: row am, k-chunk kq*8
    int am = tid & 31, kq = tid >> 5;
    int gb = m0 + am;
    const float* arow = x + ((size_t)gb * T + (T - 1)) * D;
    float ascale = td[gb * T + (T - 1)];
    // B fill (NN, Aqk row-major): k-row br, n-chunk bnq
    int br = tid >> 2, bnq = (tid & 3) * 16;
    bool do_s = (blockIdx.x == 0);
    float du = 0.f, dq = 0.f;

    u64 acc[8] = {};

    float4 aP0 = *(const float4*)(arow + kq * 8);
    float4 aP1 = *(const float4*)(arow + kq * 8 + 4);
    const float* bp0 = g_Aqk + (size_t)br * D + n0 + bnq;
    float4 bP0 = *(const float4*)(bp0);
    float4 bP1 = *(const float4*)(bp0 + 4);
    float4 bP2 = *(const float4*)(bp0 + 8);
    float4 bP3 = *(const float4*)(bp0 + 12);

    for (int k0 = 0; k0 < D; k0 += 32) {
        float av[8] = {aP0.x, aP0.y, aP0.z, aP0.w, aP1.x, aP1.y, aP1.z, aP1.w};
        float bvv[16] = {bP0.x, bP0.y, bP0.z, bP0.w, bP1.x, bP1.y, bP1.z, bP1.w,
                         bP2.x, bP2.y, bP2.z, bP2.w, bP3.x, bP3.y, bP3.z, bP3.w};
        __syncthreads();
        #pragma unroll
        for (int i = 0; i < 8; i++)
            As[(kq * 8 + i) * 32 + am] = av[i] * ascale;
        #pragma unroll
        for (int j = 0; j < 16; j++)
            Bs2[br * 64 + bnq + j] = pack_dup(bvv[j]);
        if (do_s) {
            float4 u0 = *(const float4*)(g_u + k0 + kq * 8);
            float4 u1 = *(const float4*)(g_u + k0 + kq * 8 + 4);
            float4 q0 = *(const float4*)(g_qrs + k0 + kq * 8);
            float4 q1 = *(const float4*)(g_qrs + k0 + kq * 8 + 4);
            float uu[8] = {u0.x, u0.y, u0.z, u0.w, u1.x, u1.y, u1.z, u1.w};
            float qq[8] = {q0.x, q0.y, q0.z, q0.w, q1.x, q1.y, q1.z, q1.w};
            #pragma unroll
            for (int i = 0; i < 8; i++) {
                float v = av[i] * ascale;
                du += v * uu[i];
                dq += v * qq[i];
            }
        }
        __syncthreads();
        if (k0 + 32 < D) {
            aP0 = *(const float4*)(arow + k0 + 32 + kq * 8);
            aP1 = *(const float4*)(arow + k0 + 32 + kq * 8 + 4);
            const float* bp = g_Aqk + (size_t)(k0 + 32 + br) * D + n0 + bnq;
            bP0 = *(const float4*)(bp);
            bP1 = *(const float4*)(bp + 4);
            bP2 = *(const float4*)(bp + 8);
            bP3 = *(const float4*)(bp + 12);
        }
        #pragma unroll
        for (int k = 0; k < 32; k++) {
            ulonglong2 ap = *(const ulonglong2*)&As[k * 32 + ty * 4];
            ulonglong2 b01 = *(const ulonglong2*)&Bs2[k * 64 + tx * 4];
            ulonglong2 b23 = *(const ulonglong2*)&Bs2[k * 64 + tx * 4 + 2];
            ffma2(acc[0], ap.x, b01.x); ffma2(acc[1], ap.x, b01.y);
            ffma2(acc[2], ap.x, b23.x); ffma2(acc[3], ap.x, b23.y);
            ffma2(acc[4], ap.y, b01.x); ffma2(acc[5], ap.y, b01.y);
            ffma2(acc[6], ap.y, b23.x); ffma2(acc[7], ap.y, b23.y);
        }
    }

    if (do_s) {
        sdu[tid] = du;
        sdq[tid] = dq;
        __syncthreads();
        if (tid < 32) {
            float tdu = sdu[tid] + sdu[tid + 32] + sdu[tid + 64] + sdu[tid + 96];
            float tdq = sdq[tid] + sdq[tid + 32] + sdq[tid + 64] + sdq[tid + 96];
            g_s1[m0 + tid] = tdu + g_scal[0];
            g_s2[m0 + tid] = tdq + g_scal[1];
        }
    }

    int gn = n0 + tx * 4;
    float4 w4 = *(const float4*)(g_wv + gn);
    float2 p0 = unpack2(acc[0]), p1 = unpack2(acc[1]), p2 = unpack2(acc[2]), p3 = unpack2(acc[3]);
    float2 p4 = unpack2(acc[4]), p5 = unpack2(acc[5]), p6 = unpack2(acc[6]), p7 = unpack2(acc[7]);
    int gm = m0 + ty * 4;
    *(float4*)&g_Y[(size_t)gm * D + gn] =
        make_float4(p0.x + w4.x, p1.x + w4.y, p2.x + w4.z, p3.x + w4.w);
    *(float4*)&g_Y[(size_t)(gm + 1) * D + gn] =
        make_float4(p0.y + w4.x, p1.y + w4.y, p2.y + w4.z, p3.y + w4.w);
    *(float4*)&g_Y[(size_t)(gm + 2) * D + gn] =
        make_float4(p4.x + w4.x, p5.x + w4.y, p6.x + w4.z, p7.x + w4.w);
    *(float4*)&g_Y[(size_t)(gm + 3) * D + gn] =
        make_float4(p4.y + w4.x, p5.y + w4.y, p6.y + w4.z, p7.y + w4.w);
}

// ---------------- K3: attn ----------------
__global__ __launch_bounds__(256, 4) void attn_kernel(const float* __restrict__ x,
                                                      const int* __restrict__ mask,
                                                      const float* __restrict__ td) {
    extern __shared__ float sm[];
    float* smx = sm;
    float* smV = sm + T * D;
    float* smtd = smV + D;
    float* smDV = smtd + 64;
    float* smw = smDV + 64;
    int* smm = (int*)(smw + 64);

    int b = blockIdx.x, tid = threadIdx.x;
    int warp = tid >> 5, lane = tid & 31;

    int mq = __ldg(mask + b * T + (T - 1));
    // Phase A: pure copy, max MLP (13 independent LDG.128 per thread)
    const float4* xin4 = (const float4*)(x + (size_t)b * T * D);
    float4* smx4 = (float4*)smx;
    #pragma unroll
    for (int i = tid; i < T * D / 4; i += 256) smx4[i] = xin4[i];
    smV[tid] = mq ? g_Y[(size_t)b * D + tid] : g_ksum[tid];
    if (tid < T) {
        smtd[tid] = td[b * T + tid];
        smm[tid] = mask[b * T + tid];
    }
    __syncthreads();

    // dots from smem
    float4 va = ((const float4*)smV)[lane];
    float4 vb = ((const float4*)smV)[lane + 32];
    for (int s = warp; s < T; s += 8) {
        float4 x1 = smx4[s * 64 + lane];
        float4 x2 = smx4[s * 64 + 32 + lane];
        float dv = dot4(x1, va) + dot4(x2, vb);
        #pragma unroll
        for (int o = 16; o > 0; o >>= 1) dv += __shfl_xor_sync(0xffffffffu, dv, o);
        if (lane == 0) smDV[s] = dv;
    }
    __syncthreads();

    if (warp == 0) {
        float s1b = g_s1[b], s2b = g_s2[b], bksum = g_scal[2];
        float v1 = -3.0e38f, v2 = -3.0e38f;
        if (lane < T) {
            int ms = smm[lane];
            float tds = smtd[lane];
            if (mq) v1 = ms ? (tds * smDV[lane] + s1b) : (NEGC * s2b);
            else    v1 = ms ? (NEGC * (tds * smDV[lane] + bksum)) : (NEGC * NEGC * (float)D);
            v1 *= INV_SQRT_D;
        }
        if (lane + 32 < T) {
            int s = lane + 32;
            int ms = smm[s];
            float tds = smtd[s];
            if (mq) v2 = ms ? (tds * smDV[s] + s1b) : (NEGC * s2b);
            else    v2 = ms ? (NEGC * (tds * smDV[s] + bksum)) : (NEGC * NEGC * (float)D);
            v2 *= INV_SQRT_D;
        }
        float m = fmaxf(v1, v2);
        #pragma unroll
        for (int o = 16; o > 0; o >>= 1) m = fmaxf(m, __shfl_xor_sync(0xffffffffu, m, o));
        float e1 = (lane < T) ? expf(v1 - m) : 0.f;
        float e2 = (lane + 32 < T) ? expf(v2 - m) : 0.f;
        float es = e1 + e2;
        #pragma unroll
        for (int o = 16; o > 0; o >>= 1) es += __shfl_xor_sync(0xffffffffu, es, o);
        float inv = 1.0f / es;
        if (lane < T) smw[lane] = e1 * inv * smtd[lane];
        if (lane + 32 < T) smw[lane + 32] = e2 * inv * smtd[lane + 32];
    }
    __syncthreads();

    int g = tid >> 6, q = tid & 63;
    float4 acc = make_float4(0.f, 0.f, 0.f, 0.f);
    for (int s = g; s < T; s += 4) {
        float w = smw[s];
        float4 xv = smx4[s * 64 + q];
        acc.x += w * xv.x; acc.y += w * xv.y; acc.z += w * xv.z; acc.w += w * xv.w;
    }
    __syncthreads();
    smx4[g * 64 + q] = acc;
    __syncthreads();
    if (tid < 64) {
        float4 p0 = smx4[tid], p1 = smx4[64 + tid];
        float4 p2 = smx4[128 + tid], p3 = smx4[192 + tid];
        float4 r = make_float4(p0.x + p1.x + p2.x + p3.x, p0.y + p1.y + p2.y + p3.y,
                               p0.z + p1.z + p2.z + p3.z, p0.w + p1.w + p2.w + p3.w);
        ((float4*)(g_Z + (size_t)b * D))[tid] = r;
    }
}

// ---------------- K4: out = Z @ Wv^T + bv ----------------
__global__ __launch_bounds__(128) void gemm_out(const float* __restrict__ Wv,
                                                const float* __restrict__ bv,
                                                float* __restrict__ out) {
    __shared__ __align__(16) float As[32 * 32];
    __shared__ __align__(16) u64 Bs2[32 * 64];
    int tid = threadIdx.x;
    int m0 = blockIdx.y * 32, n0 = blockIdx.x * 64;
    int tx = tid & 15, ty = tid >> 4;

    int am = tid & 31, kq = tid >> 5;
    const float* arow = g_Z + (size_t)(m0 + am) * D;
    // B fill (NT, Wv [n][k]): n-row bn, k-half bkh*16
    int bn = tid & 63, bkh = tid >> 6;
    const float* brow = Wv + (size_t)(n0 + bn) * D;

    u64 acc[8] = {};

    float4 aP0 = *(const float4*)(arow + kq * 8);
    float4 aP1 = *(const float4*)(arow + kq * 8 + 4);
    float4 bP0 = *(const float4*)(brow + bkh * 16);
    float4 bP1 = *(const float4*)(brow + bkh * 16 + 4);
    float4 bP2 = *(const float4*)(brow + bkh * 16 + 8);
    float4 bP3 = *(const float4*)(brow + bkh * 16 + 12);

    for (int k0 = 0; k0 < D; k0 += 32) {
        float av[8] = {aP0.x, aP0.y, aP0.z, aP0.w, aP1.x, aP1.y, aP1.z, aP1.w};
        float bvv[16] = {bP0.x, bP0.y, bP0.z, bP0.w, bP1.x, bP1.y, bP1.z, bP1.w,
                         bP2.x, bP2.y, bP2.z, bP2.w, bP3.x, bP3.y, bP3.z, bP3.w};
        __syncthreads();
        #pragma unroll
        for (int i = 0; i < 8; i++)
            As[(kq * 8 + i) * 32 + am] = av[i];
        #pragma unroll
        for (int j = 0; j < 16; j++)
            Bs2[(bkh * 16 + j) * 64 + bn] = pack_dup(bvv[j]);
        __syncthreads();
        if (k0 + 32 < D) {
            aP0 = *(const float4*)(arow + k0 + 32 + kq * 8);
            aP1 = *(const float4*)(arow + k0 + 32 + kq * 8 + 4);
            bP0 = *(const float4*)(brow + k0 + 32 + bkh * 16);
            bP1 = *(const float4*)(brow + k0 + 32 + bkh * 16 + 4);
            bP2 = *(const float4*)(brow + k0 + 32 + bkh * 16 + 8);
            bP3 = *(const float4*)(brow + k0 + 32 + bkh * 16 + 12);
        }
        #pragma unroll
        for (int k = 0; k < 32; k++) {
            ulonglong2 ap = *(const ulonglong2*)&As[k * 32 + ty * 4];
            ulonglong2 b01 = *(const ulonglong2*)&Bs2[k * 64 + tx * 4];
            ulonglong2 b23 = *(const ulonglong2*)&Bs2[k * 64 + tx * 4 + 2];
            ffma2(acc[0], ap.x, b01.x); ffma2(acc[1], ap.x, b01.y);
            ffma2(acc[2], ap.x, b23.x); ffma2(acc[3], ap.x, b23.y);
            ffma2(acc[4], ap.y, b01.x); ffma2(acc[5], ap.y, b01.y);
            ffma2(acc[6], ap.y, b23.x); ffma2(acc[7], ap.y, b23.y);
        }
    }

    int gn = n0 + tx * 4;
    float4 b4 = *(const float4*)(bv + gn);
    float2 p0 = unpack2(acc[0]), p1 = unpack2(acc[1]), p2 = unpack2(acc[2]), p3 = unpack2(acc[3]);
    float2 p4 = unpack2(acc[4]), p5 = unpack2(acc[5]), p6 = unpack2(acc[6]), p7 = unpack2(acc[7]);
    int gm = m0 + ty * 4;
    *(float4*)&out[(size_t)gm * D + gn] =
        make_float4(p0.x + b4.x, p1.x + b4.y, p2.x + b4.z, p3.x + b4.w);
    *(float4*)&out[(size_t)(gm + 1) * D + gn] =
        make_float4(p0.y + b4.x, p1.y + b4.y, p2.y + b4.z, p3.y + b4.w);
    *(float4*)&out[(size_t)(gm + 2) * D + gn] =
        make_float4(p4.x + b4.x, p5.x + b4.y, p6.x + b4.z, p7.x + b4.w);
    *(float4*)&out[(size_t)(gm + 3) * D + gn] =
        make_float4(p4.y + b4.x, p5.y + b4.y, p6.y + b4.z, p7.y + b4.w);
}

// ---------------- launch ----------------
extern "C" void kernel_launch(void* const* d_in, const int* in_sizes, int n_in,
                              void* d_out, int out_size) {
    const float* x = (const float*)d_in[0];
    const int* mask = (const int*)d_in[1];
    const float* td = (const float*)d_in[2];
    const float* Wq = (const float*)d_in[3];
    const float* bq = (const float*)d_in[4];
    const float* Wk = (const float*)d_in[5];
    const float* bk = (const float*)d_in[6];
    const float* Wv = (const float*)d_in[7];
    const float* bv = (const float*)d_in[8];
    float* out = (float*)d_out;

    const int attn_smem = (T * D + D + 64 + 64 + 64 + 64) * 4;  // 53.25 KB
    cudaFuncSetAttribute(attn_kernel, cudaFuncAttributeMaxDynamicSharedMemorySize, attn_smem);

    prep_kernel<<<dim3(16, 16), 256>>>(Wq, bq, Wk, bk);
    gemm_y<<<dim3(4, 64), 128>>>(x, td);
    attn_kernel<<<BATCH, 256, attn_smem>>>(x, mask, td);
    gemm_out<<<dim3(4, 64), 128>>>(Wv, bv, out);
}

// round 6
// speedup vs baseline: 1.6353x; 1.6353x over previous
#include <cuda_runtime.h>
#include <math.h>

#define BATCH 2048
#define T 50
#define D 256
#define NEGC (-100000.0f)
#define INV_SQRT_D 0.0625f

typedef unsigned long long u64;

// ---------------- device scratch ----------------
__device__ float g_Aqk[D * D];
__device__ float g_u[D];
__device__ float g_qrs[D];
__device__ float g_wv[D];
__device__ float g_ksum[D];
__device__ float g_scal[3];
__device__ float g_Z[BATCH * D];
__device__ float g_Yp[4 * BATCH * D];   // split-K partials of Y
__device__ float g_Op[4 * BATCH * D];   // split-K partials of out

// ---------------- f32x2 helpers ----------------
__device__ __forceinline__ void ffma2(u64& d, u64 a, u64 b) {
    asm("fma.rn.f32x2 %0, %1, %2, %0;" : "+l"(d) : "l"(a), "l"(b));
}
__device__ __forceinline__ float2 unpack2(u64 v) {
    float2 r;
    asm("mov.b64 {%0, %1}, %2;" : "=f"(r.x), "=f"(r.y) : "l"(v));
    return r;
}
__device__ __forceinline__ u64 pack_dup(float v) {
    u64 r;
    asm("mov.b64 %0, {%1, %1};" : "=l"(r) : "f"(v));
    return r;
}
__device__ __forceinline__ float dot4(float4 a, float4 b) {
    return a.x * b.x + a.y * b.y + a.z * b.z + a.w * b.w;
}

// ---------------- K1: prep (Aqk + small vectors), grid 16x16 ----------------
// Full-K smem tiles, single sync, front-loaded MLP.
__global__ __launch_bounds__(256) void prep_kernel(const float* __restrict__ Wq,
                                                   const float* __restrict__ bq,
                                                   const float* __restrict__ Wk,
                                                   const float* __restrict__ bk) {
    __shared__ __align__(16) float Aw[256 * 16];
    __shared__ __align__(16) float Bw[256 * 16];
    __shared__ float s_bq[256], s_bk[256];
    int tid = threadIdx.x;
    int tx = tid & 15, ty = tid >> 4;
    int m0 = blockIdx.y * 16, n0 = blockIdx.x * 16;

    // fill: 4 float4 per array per thread
    int e0 = tid >> 2, q = tid & 3;
    #pragma unroll
    for (int j = 0; j < 4; j++) {
        int e = e0 + 64 * j;
        float4 a = *(const float4*)(Wq + (size_t)e * D + m0 + q * 4);
        float4 b = *(const float4*)(Wk + (size_t)e * D + n0 + q * 4);
        *(float4*)&Aw[e * 16 + q * 4] = a;
        *(float4*)&Bw[e * 16 + q * 4] = b;
    }
    s_bq[tid] = bq[tid];
    s_bk[tid] = bk[tid];
    __syncthreads();

    float acc = 0.f;
    #pragma unroll 8
    for (int e = 0; e < 256; e++) acc += Aw[e * 16 + ty] * Bw[e * 16 + tx];
    g_Aqk[(m0 + ty) * D + n0 + tx] = acc;

    if (blockIdx.x == 0 && ty == 0) {  // u, qrs for columns m0+tx
        float su = 0.f, sq = 0.f;
        #pragma unroll 8
        for (int e = 0; e < 256; e++) {
            float w = Aw[e * 16 + tx];
            su += s_bk[e] * w;
            sq += w;
        }
        g_u[m0 + tx] = su;
        g_qrs[m0 + tx] = sq;
    }
    if (blockIdx.y == 0 && ty == 1) {  // wv, ksum for columns n0+tx
        float sw = 0.f, sk = 0.f;
        #pragma unroll 8
        for (int e = 0; e < 256; e++) {
            float w = Bw[e * 16 + tx];
            sw += s_bq[e] * w;
            sk += w;
        }
        g_wv[n0 + tx] = sw;
        g_ksum[n0 + tx] = sk;
    }
    if (blockIdx.x == 0 && blockIdx.y == 0 && tid < 32) {
        float a0 = 0.f, a1 = 0.f, a2 = 0.f;
        #pragma unroll
        for (int j = 0; j < 8; j++) {
            float qv = s_bq[tid + 32 * j], kv = s_bk[tid + 32 * j];
            a0 += qv * kv; a1 += qv; a2 += kv;
        }
        #pragma unroll
        for (int o = 16; o > 0; o >>= 1) {
            a0 += __shfl_xor_sync(0xffffffffu, a0, o);
            a1 += __shfl_xor_sync(0xffffffffu, a1, o);
            a2 += __shfl_xor_sync(0xffffffffu, a2, o);
        }
        if (tid == 0) { g_scal[0] = a0; g_scal[1] = a1; g_scal[2] = a2; }
    }
}

// ---------------- split-K GEMM: 128m x 64n x 64k per CTA ----------------
// ASRC: 0 = x last rows * td    1 = g_Z
// BSRC: 0 = g_Aqk (NN)         1 = param B (NT, B[n][k])
// PDST: 0 = g_Yp               1 = g_Op
template <int ASRC, int BSRC, int PDST>
__global__ __launch_bounds__(256) void gemm_sk(const float* __restrict__ x,
                                               const float* __restrict__ td,
                                               const float* __restrict__ Bp) {
    __shared__ __align__(16) float As[64 * 128];  // [k][m] 32KB
    __shared__ __align__(16) float Bs[64 * 64];   // [k][n] 16KB
    int tid = threadIdx.x;
    int n0 = blockIdx.x * 64, m0 = blockIdx.y * 128, ks = blockIdx.z * 64;

    // ---- A fill: row r, k-chunk kc (32 k per thread half) ----
    {
        int r = tid & 127, kc = (tid >> 7) * 32;
        const float* arow;
        float asc = 1.0f;
        if (ASRC == 0) {
            int gb = m0 + r;
            arow = x + ((size_t)gb * T + (T - 1)) * D;
            asc = td[gb * T + (T - 1)];
        } else {
            arow = g_Z + (size_t)(m0 + r) * D;
        }
        float4 v[8];
        #pragma unroll
        for (int i = 0; i < 8; i++) v[i] = *(const float4*)(arow + ks + kc + i * 4);
        #pragma unroll
        for (int i = 0; i < 8; i++) {
            As[(kc + i * 4 + 0) * 128 + r] = v[i].x * asc;
            As[(kc + i * 4 + 1) * 128 + r] = v[i].y * asc;
            As[(kc + i * 4 + 2) * 128 + r] = v[i].z * asc;
            As[(kc + i * 4 + 3) * 128 + r] = v[i].w * asc;
        }
    }
    // ---- B fill ----
    if (BSRC == 0) {  // NN from g_Aqk[k][n]
        int q = tid & 15, kr0 = tid >> 4;
        #pragma unroll
        for (int p = 0; p < 4; p++) {
            int kr = kr0 + p * 16;
            float4 v = *(const float4*)(g_Aqk + (size_t)(ks + kr) * D + n0 + q * 4);
            *(float4*)&Bs[kr * 64 + q * 4] = v;
        }
    } else {  // NT from Bp[n][k]
        int nr = tid & 63, kq = (tid >> 6) * 16;
        const float* brow = Bp + (size_t)(n0 + nr) * D + ks + kq;
        float4 v0 = *(const float4*)(brow);
        float4 v1 = *(const float4*)(brow + 4);
        float4 v2 = *(const float4*)(brow + 8);
        float4 v3 = *(const float4*)(brow + 12);
        float vs[16] = {v0.x, v0.y, v0.z, v0.w, v1.x, v1.y, v1.z, v1.w,
                        v2.x, v2.y, v2.z, v2.w, v3.x, v3.y, v3.z, v3.w};
        #pragma unroll
        for (int i = 0; i < 16; i++) Bs[(kq + i) * 64 + nr] = vs[i];
    }
    __syncthreads();

    // ---- inner loop: thread tile 8m x 4n, f32x2 over m-pairs ----
    int tx = tid & 15, ty = tid >> 4;
    u64 acc[4][4] = {};
    #pragma unroll 2
    for (int kk = 0; kk < 64; kk += 16) {
        #pragma unroll
        for (int k2 = 0; k2 < 16; k2++) {
            int k = kk + k2;
            ulonglong2 a01 = *(const ulonglong2*)&As[k * 128 + ty * 8];
            ulonglong2 a23 = *(const ulonglong2*)&As[k * 128 + ty * 8 + 4];
            float4 b4 = *(const float4*)&Bs[k * 64 + tx * 4];
            u64 b0 = pack_dup(b4.x), b1 = pack_dup(b4.y);
            u64 b2 = pack_dup(b4.z), b3 = pack_dup(b4.w);
            ffma2(acc[0][0], a01.x, b0); ffma2(acc[0][1], a01.x, b1);
            ffma2(acc[0][2], a01.x, b2); ffma2(acc[0][3], a01.x, b3);
            ffma2(acc[1][0], a01.y, b0); ffma2(acc[1][1], a01.y, b1);
            ffma2(acc[1][2], a01.y, b2); ffma2(acc[1][3], a01.y, b3);
            ffma2(acc[2][0], a23.x, b0); ffma2(acc[2][1], a23.x, b1);
            ffma2(acc[2][2], a23.x, b2); ffma2(acc[2][3], a23.x, b3);
            ffma2(acc[3][0], a23.y, b0); ffma2(acc[3][1], a23.y, b1);
            ffma2(acc[3][2], a23.y, b2); ffma2(acc[3][3], a23.y, b3);
        }
    }

    // ---- write partial tile ----
    float* part = (PDST == 0) ? g_Yp : g_Op;
    int gn = n0 + tx * 4;
    int gmb = m0 + ty * 8;
    size_t base = ((size_t)blockIdx.z * BATCH + gmb) * D + gn;
    #pragma unroll
    for (int mp = 0; mp < 4; mp++) {
        float2 p0 = unpack2(acc[mp][0]), p1 = unpack2(acc[mp][1]);
        float2 p2 = unpack2(acc[mp][2]), p3 = unpack2(acc[mp][3]);
        *(float4*)&part[base + (size_t)(2 * mp) * D] = make_float4(p0.x, p1.x, p2.x, p3.x);
        *(float4*)&part[base + (size_t)(2 * mp + 1) * D] = make_float4(p0.y, p1.y, p2.y, p3.y);
    }
}

// ---------------- K3: attn ----------------
__global__ __launch_bounds__(256, 4) void attn_kernel(const float* __restrict__ x,
                                                      const int* __restrict__ mask,
                                                      const float* __restrict__ td) {
    extern __shared__ float sm[];
    float* smx = sm;                 // 50*256
    float* smV = sm + T * D;         // 256
    float* smtd = smV + D;           // 64
    float* smDV = smtd + 64;         // 64 (50,51 hold dU,dQ)
    float* smw = smDV + 64;          // 64
    int* smm = (int*)(smw + 64);     // 64

    int b = blockIdx.x, tid = threadIdx.x;
    int warp = tid >> 5, lane = tid & 31;

    int mq = __ldg(mask + b * T + (T - 1));
    const float4* xin4 = (const float4*)(x + (size_t)b * T * D);
    float4* smx4 = (float4*)smx;
    #pragma unroll
    for (int i = tid; i < T * D / 4; i += 256) smx4[i] = xin4[i];
    if (mq) {
        int idx = b * D + tid;
        smV[tid] = g_Yp[idx] + g_Yp[BATCH * D + idx] + g_Yp[2 * BATCH * D + idx] +
                   g_Yp[3 * BATCH * D + idx] + g_wv[tid];
    } else {
        smV[tid] = g_ksum[tid];
    }
    if (tid < T) {
        smtd[tid] = td[b * T + tid];
        smm[tid] = mask[b * T + tid];
    }
    __syncthreads();

    // dots with smV; warps 2/3 additionally compute dU/dQ (x_last . u / qrs)
    float4 va = ((const float4*)smV)[lane];
    float4 vb = ((const float4*)smV)[lane + 32];
    for (int s = warp; s < T; s += 8) {
        float4 x1 = smx4[s * 64 + lane];
        float4 x2 = smx4[s * 64 + 32 + lane];
        float dv = dot4(x1, va) + dot4(x2, vb);
        #pragma unroll
        for (int o = 16; o > 0; o >>= 1) dv += __shfl_xor_sync(0xffffffffu, dv, o);
        if (lane == 0) smDV[s] = dv;
    }
    if (warp == 2 || warp == 3) {
        const float4* w4 = (warp == 2) ? (const float4*)g_u : (const float4*)g_qrs;
        float4 x1 = smx4[(T - 1) * 64 + lane];
        float4 x2 = smx4[(T - 1) * 64 + 32 + lane];
        float dv = dot4(x1, __ldg(w4 + lane)) + dot4(x2, __ldg(w4 + lane + 32));
        #pragma unroll
        for (int o = 16; o > 0; o >>= 1) dv += __shfl_xor_sync(0xffffffffu, dv, o);
        if (lane == 0) smDV[T + (warp - 2)] = dv;
    }
    __syncthreads();

    if (warp == 0) {
        float tdl = smtd[T - 1];
        float s1b = tdl * smDV[T] + g_scal[0];
        float s2b = tdl * smDV[T + 1] + g_scal[1];
        float bksum = g_scal[2];
        float v1 = -3.0e38f, v2 = -3.0e38f;
        if (lane < T) {
            int ms = smm[lane];
            float tds = smtd[lane];
            if (mq) v1 = ms ? (tds * smDV[lane] + s1b) : (NEGC * s2b);
            else    v1 = ms ? (NEGC * (tds * smDV[lane] + bksum)) : (NEGC * NEGC * (float)D);
            v1 *= INV_SQRT_D;
        }
        if (lane + 32 < T) {
            int s = lane + 32;
            int ms = smm[s];
            float tds = smtd[s];
            if (mq) v2 = ms ? (tds * smDV[s] + s1b) : (NEGC * s2b);
            else    v2 = ms ? (NEGC * (tds * smDV[s] + bksum)) : (NEGC * NEGC * (float)D);
            v2 *= INV_SQRT_D;
        }
        float m = fmaxf(v1, v2);
        #pragma unroll
        for (int o = 16; o > 0; o >>= 1) m = fmaxf(m, __shfl_xor_sync(0xffffffffu, m, o));
        float e1 = (lane < T) ? expf(v1 - m) : 0.f;
        float e2 = (lane + 32 < T) ? expf(v2 - m) : 0.f;
        float es = e1 + e2;
        #pragma unroll
        for (int o = 16; o > 0; o >>= 1) es += __shfl_xor_sync(0xffffffffu, es, o);
        float inv = 1.0f / es;
        if (lane < T) smw[lane] = e1 * inv * smtd[lane];
        if (lane + 32 < T) smw[lane + 32] = e2 * inv * smtd[lane + 32];
    }
    __syncthreads();

    int g = tid >> 6, q = tid & 63;
    float4 acc = make_float4(0.f, 0.f, 0.f, 0.f);
    for (int s = g; s < T; s += 4) {
        float w = smw[s];
        float4 xv = smx4[s * 64 + q];
        acc.x += w * xv.x; acc.y += w * xv.y; acc.z += w * xv.z; acc.w += w * xv.w;
    }
    __syncthreads();
    smx4[g * 64 + q] = acc;
    __syncthreads();
    if (tid < 64) {
        float4 p0 = smx4[tid], p1 = smx4[64 + tid];
        float4 p2 = smx4[128 + tid], p3 = smx4[192 + tid];
        float4 r = make_float4(p0.x + p1.x + p2.x + p3.x, p0.y + p1.y + p2.y + p3.y,
                               p0.z + p1.z + p2.z + p3.z, p0.w + p1.w + p2.w + p3.w);
        ((float4*)(g_Z + (size_t)b * D))[tid] = r;
    }
}

// ---------------- K5: reduce out partials + bias ----------------
__global__ __launch_bounds__(256) void reduce_out(const float* __restrict__ bv,
                                                  float* __restrict__ out) {
    int i = blockIdx.x * 256 + threadIdx.x;  // float4 index over [2048*256/4]
    const float4* p = (const float4*)g_Op;
    const int Q = BATCH * D / 4;  // 131072
    float4 a = p[i], b = p[i + Q], c = p[i + 2 * Q], d = p[i + 3 * Q];
    float4 bb = ((const float4*)bv)[i & 63];
    float4 r = make_float4(a.x + b.x + c.x + d.x + bb.x, a.y + b.y + c.y + d.y + bb.y,
                           a.z + b.z + c.z + d.z + bb.z, a.w + b.w + c.w + d.w + bb.w);
    ((float4*)out)[i] = r;
}

// ---------------- launch ----------------
extern "C" void kernel_launch(void* const* d_in, const int* in_sizes, int n_in,
                              void* d_out, int out_size) {
    const float* x = (const float*)d_in[0];
    const int* mask = (const int*)d_in[1];
    const float* td = (const float*)d_in[2];
    const float* Wq = (const float*)d_in[3];
    const float* bq = (const float*)d_in[4];
    const float* Wk = (const float*)d_in[5];
    const float* bk = (const float*)d_in[6];
    const float* Wv = (const float*)d_in[7];
    const float* bv = (const float*)d_in[8];
    float* out = (float*)d_out;

    const int attn_smem = (T * D + D + 64 + 64 + 64 + 64) * 4;  // 53.25 KB
    cudaFuncSetAttribute(attn_kernel, cudaFuncAttributeMaxDynamicSharedMemorySize, attn_smem);

    dim3 gsk(4, 16, 4);
    prep_kernel<<<dim3(16, 16), 256>>>(Wq, bq, Wk, bk);
    gemm_sk<0, 0, 0><<<gsk, 256>>>(x, td, nullptr);   // Y partials
    attn_kernel<<<BATCH, 256, attn_smem>>>(x, mask, td);
    gemm_sk<1, 1, 1><<<gsk, 256>>>(nullptr, nullptr, Wv);  // out partials
    reduce_out<<<BATCH * D / 4 / 256, 256>>>(bv, out);
}